// round 14
// baseline (speedup 1.0000x reference)
#include <cuda_runtime.h>
#include <cuda_bf16.h>
#include <cstdint>

#define NN 50000
#define F 128

// ---------------- scratch (static __device__, no allocation) ----------------
__device__ int   g_degOut[NN];
__device__ int   g_degIn[NN];
__device__ float g_Sx[NN];
__device__ float g_Sd[NN];
__device__ float g_dinv[NN];   // rsqrt(in_deg + 1)  (GCN norm, self-loops included)
__device__ float g_cinv[NN];   // 1 / max(in_deg, 1) (SAGE mean)
__device__ float g_a1[NN * F];
__device__ float g_agg[NN * F];

// ---------------- K0: zero counters, init output with n*b_v2 ----------------
__global__ void k0_zero(int n, float* __restrict__ out, const float* __restrict__ b_v2) {
    int i = blockIdx.x * blockDim.x + threadIdx.x;
    if (i < n) {
        g_degOut[i] = 0;
        g_degIn[i]  = 0;
        g_Sx[i] = 0.f;
        g_Sd[i] = 0.f;
    }
    if (i == 0) out[0] = (float)n * b_v2[0];
}

// ---------------- K1: degree counts ----------------
__global__ void k1_deg(const int* __restrict__ ei, int E) {
    int e = blockIdx.x * blockDim.x + threadIdx.x;
    if (e < E) {
        atomicAdd(&g_degOut[ei[e]], 1);
        atomicAdd(&g_degIn[ei[E + e]], 1);
    }
}

// ---------------- K2: norms ----------------
__global__ void k2_norm(int n) {
    int i = blockIdx.x * blockDim.x + threadIdx.x;
    if (i < n) {
        float din = (float)g_degIn[i];
        g_dinv[i] = rsqrtf(din + 1.0f);          // deg over d2 includes self loop
        g_cinv[i] = 1.0f / fmaxf(din, 1.0f);     // SAGE mean denominator
    }
}

// ---------------- K3: rank-2 GCN edge aggregation (2 scalar atomics/edge) ----
__global__ void k3_gcn_edges(const int* __restrict__ ei, const float* __restrict__ x, int E) {
    int e = blockIdx.x * blockDim.x + threadIdx.x;
    if (e < E) {
        int s = ei[e];
        int d = ei[E + e];
        float w = g_dinv[s] * g_dinv[d];
        atomicAdd(&g_Sx[d], w * x[s]);
        atomicAdd(&g_Sd[d], w * (float)g_degOut[s]);
    }
}

// ---------------- K4: materialize a1 = relu(GCN), zero agg --------------
__global__ void k4_a1(const float* __restrict__ x, const float* __restrict__ W_gcn,
                      const float* __restrict__ b_gcn, int n) {
    int idx = blockIdx.x * blockDim.x + threadIdx.x;
    if (idx < n * F) {
        int i = idx >> 7;
        int k = idx & 127;
        float di = g_dinv[i];
        float di2 = di * di;
        float sx = g_Sx[i] + di2 * x[i];                      // self-loop term
        float sd = g_Sd[i] + di2 * (float)g_degOut[i];
        float v = sx * W_gcn[k] + sd * W_gcn[F + k] + b_gcn[k];
        g_a1[idx] = fmaxf(v, 0.f);
        g_agg[idx] = 0.f;
    }
}

// ---------------- K5: SAGE scatter — warp per edge, vectorized reductions ----
__device__ __forceinline__ void red_add_v4(float* addr, float4 v) {
    asm volatile("red.global.add.v4.f32 [%0], {%1, %2, %3, %4};"
                 :: "l"(addr), "f"(v.x), "f"(v.y), "f"(v.z), "f"(v.w) : "memory");
}

__global__ void __launch_bounds__(256) k5_scatter(const int* __restrict__ ei, int E) {
    int gw = blockIdx.x * 8 + (threadIdx.x >> 5);  // global warp id = edge id
    int lane = threadIdx.x & 31;
    if (gw < E) {
        int s = ei[gw];
        int d = ei[E + gw];
        float4 v = reinterpret_cast<const float4*>(g_a1)[s * 32 + lane];
        red_add_v4(&g_agg[d * F + lane * 4], v);
    }
}

// ---------------- K6: persistent fused GEMM + value head + sum --------------
// smem float offsets
#define OFF_W    0          // [256][128]   W_L ; W_R  (32768)
#define OFF_V1   32768      // [128][64]    W_v1       (8192)
#define OFF_VEC  40960      // [256][36]    node tile, k-major (9216)  -- aliased by a2 tile
#define OFF_BL   50176      // [128] b_sage_l
#define OFF_BV1  50304      // [64]  b_v1
#define OFF_V2   50368      // [64]  W_v2
#define OFF_RED  50432      // [256] block reduce
#define SMEM_FLOATS 50688
#define SMEM_BYTES  (SMEM_FLOATS * 4)

__global__ void __launch_bounds__(256, 1) k6_fused(
    const float* __restrict__ W_l, const float* __restrict__ b_l,
    const float* __restrict__ W_r, const float* __restrict__ W_v1,
    const float* __restrict__ b_v1, const float* __restrict__ W_v2,
    int n, float* __restrict__ out)
{
    extern __shared__ float sm[];
    float* sW   = sm + OFF_W;
    float* sV1  = sm + OFF_V1;
    float* sVec = sm + OFF_VEC;   // [k][nloc], row stride 36
    float* sA2  = sm + OFF_VEC;   // alias: [j][nloc], row stride 36
    float* sBL  = sm + OFF_BL;
    float* sBV1 = sm + OFF_BV1;
    float* sV2  = sm + OFF_V2;
    float* sRed = sm + OFF_RED;

    int tid = threadIdx.x;

    // stage weights once per block (persistent blocks)
    for (int i = tid; i < 16384; i += 256) { sW[i] = W_l[i]; sW[16384 + i] = W_r[i]; }
    for (int i = tid; i < 8192;  i += 256) sV1[i] = W_v1[i];
    if (tid < 128) sBL[tid] = b_l[tid];
    if (tid < 64)  { sBV1[tid] = b_v1[tid]; sV2[tid] = W_v2[tid]; }
    __syncthreads();

    const int og  = tid & 31;   // output group (4 outs)
    const int ng  = tid >> 5;   // node group (4 nodes)
    const int ug  = tid & 15;   // hidden-unit group (4 units)
    const int ng2 = tid >> 4;   // node group for head (2 nodes)

    float vsum = 0.f;
    int nTiles = (n + 31) >> 5;

    for (int tile = blockIdx.x; tile < nTiles; tile += gridDim.x) {
        int base = tile << 5;

        // ---- load vec tile [256][32]: k<128 = agg/cnt, k>=128 = a1 ----
        {
            int nloc0 = tid >> 7;      // 0/1
            int k0 = tid & 127;
            #pragma unroll
            for (int it = 0; it < 16; ++it) {
                int nl = it * 2 + nloc0;
                int node = base + nl;
                float av = 0.f, bv = 0.f;
                if (node < n) {
                    av = g_agg[node * F + k0] * g_cinv[node];
                    bv = g_a1[node * F + k0];
                }
                sVec[k0 * 36 + nl]        = av;
                sVec[(128 + k0) * 36 + nl] = bv;
            }
        }
        __syncthreads();

        // ---- a2 GEMM: 32 nodes x 128 outs, K=256, 4x4 register tile ----
        float acc[4][4] = {};
        const float* wp = sW + og * 4;
        const float* vp = sVec + ng * 4;
        #pragma unroll 4
        for (int k = 0; k < 256; ++k) {
            float4 v = *reinterpret_cast<const float4*>(vp + k * 36);
            float4 w = *reinterpret_cast<const float4*>(wp + k * 128);
            float vv[4] = {v.x, v.y, v.z, v.w};
            float ww[4] = {w.x, w.y, w.z, w.w};
            #pragma unroll
            for (int i = 0; i < 4; ++i)
                #pragma unroll
                for (int j = 0; j < 4; ++j)
                    acc[i][j] += vv[i] * ww[j];
        }
        __syncthreads();   // all reads of sVec done (sA2 aliases it)

        // ---- write a2 (+bias) transposed [out][node] ----
        #pragma unroll
        for (int j = 0; j < 4; ++j) {
            float bj = sBL[og * 4 + j];
            #pragma unroll
            for (int i = 0; i < 4; ++i)
                sA2[(og * 4 + j) * 36 + (ng * 4 + i)] = acc[i][j] + bj;
        }
        __syncthreads();

        // ---- value head: hidden = relu(a2 @ W_v1 + b_v1); v = hidden @ W_v2 ----
        float acc2[2][4] = {};
        const float* ap  = sA2 + ng2 * 2;
        const float* w1p = sV1 + ug * 4;
        #pragma unroll 4
        for (int k = 0; k < 128; ++k) {
            float2 a = *reinterpret_cast<const float2*>(ap + k * 36);
            float4 w = *reinterpret_cast<const float4*>(w1p + k * 64);
            float aa[2] = {a.x, a.y};
            float ww[4] = {w.x, w.y, w.z, w.w};
            #pragma unroll
            for (int i = 0; i < 2; ++i)
                #pragma unroll
                for (int j = 0; j < 4; ++j)
                    acc2[i][j] += aa[i] * ww[j];
        }
        #pragma unroll
        for (int i = 0; i < 2; ++i) {
            int node = base + ng2 * 2 + i;
            if (node < n) {
                float s = 0.f;
                #pragma unroll
                for (int j = 0; j < 4; ++j) {
                    float h = fmaxf(acc2[i][j] + sBV1[ug * 4 + j], 0.f);
                    s += h * sV2[ug * 4 + j];
                }
                vsum += s;
            }
        }
        __syncthreads();   // protect sVec/sA2 before next tile's loads
    }

    // ---- block reduce + single atomic into out ----
    sRed[tid] = vsum;
    __syncthreads();
    for (int s = 128; s > 0; s >>= 1) {
        if (tid < s) sRed[tid] += sRed[tid + s];
        __syncthreads();
    }
    if (tid == 0) atomicAdd(out, sRed[0]);
}

// ---------------- launch ----------------
extern "C" void kernel_launch(void* const* d_in, const int* in_sizes, int n_in,
                              void* d_out, int out_size) {
    const float* x      = (const float*)d_in[0];
    const int*   ei     = (const int*)  d_in[1];
    const float* W_gcn  = (const float*)d_in[2];
    const float* b_gcn  = (const float*)d_in[3];
    const float* W_l    = (const float*)d_in[4];
    const float* b_l    = (const float*)d_in[5];
    const float* W_r    = (const float*)d_in[6];
    const float* W_v1   = (const float*)d_in[7];
    const float* b_v1   = (const float*)d_in[8];
    const float* W_v2   = (const float*)d_in[9];
    const float* b_v2   = (const float*)d_in[10];

    int n = in_sizes[0];
    int E = in_sizes[1] / 2;
    float* out = (float*)d_out;

    int nsm = 148;
    {
        int dev = 0;
        if (cudaGetDevice(&dev) == cudaSuccess) {
            int v = 0;
            if (cudaDeviceGetAttribute(&v, cudaDevAttrMultiProcessorCount, dev) == cudaSuccess && v > 0)
                nsm = v;
        }
    }
    cudaFuncSetAttribute(k6_fused, cudaFuncAttributeMaxDynamicSharedMemorySize, SMEM_BYTES);

    k0_zero<<<(n + 255) / 256, 256>>>(n, out, b_v2);
    k1_deg<<<(E + 255) / 256, 256>>>(ei, E);
    k2_norm<<<(n + 255) / 256, 256>>>(n);
    k3_gcn_edges<<<(E + 255) / 256, 256>>>(ei, x, E);
    k4_a1<<<(n * F + 255) / 256, 256>>>(x, W_gcn, b_gcn, n);
    k5_scatter<<<(E + 7) / 8, 256>>>(ei, E);   // one warp per edge
    k6_fused<<<nsm, 256, SMEM_BYTES>>>(W_l, b_l, W_r, W_v1, b_v1, W_v2, n, out);
}

// round 15
// speedup vs baseline: 1.0018x; 1.0018x over previous
#include <cuda_runtime.h>
#include <cuda_bf16.h>
#include <cstdint>

#define NN 50000
#define F 128

// ---------------- scratch (static __device__, no allocation) ----------------
__device__ int   g_degOut[NN];
__device__ int   g_degIn[NN];
__device__ float g_Sx[NN];
__device__ float g_Sd[NN];
__device__ float g_dinv[NN];   // rsqrt(in_deg + 1)  (GCN norm, self-loops included)
__device__ float g_cinv[NN];   // 1 / max(in_deg, 1) (SAGE mean)
__device__ float g_a1[NN * F];
__device__ float g_agg[NN * F];

// ---------------- K0: zero counters, init output with n*b_v2 ----------------
__global__ void k0_zero(int n, float* __restrict__ out, const float* __restrict__ b_v2) {
    int i = blockIdx.x * blockDim.x + threadIdx.x;
    if (i < n) {
        g_degOut[i] = 0;
        g_degIn[i]  = 0;
        g_Sx[i] = 0.f;
        g_Sd[i] = 0.f;
    }
    if (i == 0) out[0] = (float)n * b_v2[0];
}

// ---------------- K1: degree counts ----------------
__global__ void k1_deg(const int* __restrict__ ei, int E) {
    int e = blockIdx.x * blockDim.x + threadIdx.x;
    if (e < E) {
        atomicAdd(&g_degOut[ei[e]], 1);
        atomicAdd(&g_degIn[ei[E + e]], 1);
    }
}

// ---------------- K2: norms ----------------
__global__ void k2_norm(int n) {
    int i = blockIdx.x * blockDim.x + threadIdx.x;
    if (i < n) {
        float din = (float)g_degIn[i];
        g_dinv[i] = rsqrtf(din + 1.0f);          // deg over d2 includes self loop
        g_cinv[i] = 1.0f / fmaxf(din, 1.0f);     // SAGE mean denominator
    }
}

// ---------------- K3: rank-2 GCN edge aggregation (2 scalar atomics/edge) ----
__global__ void k3_gcn_edges(const int* __restrict__ ei, const float* __restrict__ x, int E) {
    int e = blockIdx.x * blockDim.x + threadIdx.x;
    if (e < E) {
        int s = ei[e];
        int d = ei[E + e];
        float w = g_dinv[s] * g_dinv[d];
        atomicAdd(&g_Sx[d], w * x[s]);
        atomicAdd(&g_Sd[d], w * (float)g_degOut[s]);
    }
}

// ---------------- K4: materialize a1 = relu(GCN), zero agg --------------
__global__ void k4_a1(const float* __restrict__ x, const float* __restrict__ W_gcn,
                      const float* __restrict__ b_gcn, int n) {
    int idx = blockIdx.x * blockDim.x + threadIdx.x;
    if (idx < n * F) {
        int i = idx >> 7;
        int k = idx & 127;
        float di = g_dinv[i];
        float di2 = di * di;
        float sx = g_Sx[i] + di2 * x[i];                      // self-loop term
        float sd = g_Sd[i] + di2 * (float)g_degOut[i];
        float v = sx * W_gcn[k] + sd * W_gcn[F + k] + b_gcn[k];
        g_a1[idx] = fmaxf(v, 0.f);
        g_agg[idx] = 0.f;
    }
}

// ---------------- K5: SAGE scatter — warp per edge, vectorized reductions ----
__device__ __forceinline__ void red_add_v4(float* addr, float4 v) {
    asm volatile("red.global.add.v4.f32 [%0], {%1, %2, %3, %4};"
                 :: "l"(addr), "f"(v.x), "f"(v.y), "f"(v.z), "f"(v.w) : "memory");
}

__global__ void __launch_bounds__(256) k5_scatter(const int* __restrict__ ei, int E) {
    int gw = blockIdx.x * 8 + (threadIdx.x >> 5);  // global warp id = edge id
    int lane = threadIdx.x & 31;
    if (gw < E) {
        int s = ei[gw];
        int d = ei[E + gw];
        float4 v = reinterpret_cast<const float4*>(g_a1)[s * 32 + lane];
        red_add_v4(&g_agg[d * F + lane * 4], v);
    }
}

// ---------------- K6: persistent fused GEMM + value head + sum --------------
// smem float offsets
#define OFF_W    0          // [256][128]   W_L ; W_R  (32768)
#define OFF_V1   32768      // [128][64]    W_v1       (8192)
#define OFF_VEC  40960      // [256][36]    node tile, k-major (9216)  -- aliased by a2 tile
#define OFF_BL   50176      // [128] b_sage_l
#define OFF_BV1  50304      // [64]  b_v1
#define OFF_V2   50368      // [64]  W_v2
#define OFF_RED  50432      // [256] block reduce
#define SMEM_FLOATS 50688
#define SMEM_BYTES  (SMEM_FLOATS * 4)

__global__ void __launch_bounds__(256, 1) k6_fused(
    const float* __restrict__ W_l, const float* __restrict__ b_l,
    const float* __restrict__ W_r, const float* __restrict__ W_v1,
    const float* __restrict__ b_v1, const float* __restrict__ W_v2,
    int n, float* __restrict__ out)
{
    extern __shared__ float sm[];
    float* sW   = sm + OFF_W;
    float* sV1  = sm + OFF_V1;
    float* sVec = sm + OFF_VEC;   // [k][nloc], row stride 36
    float* sA2  = sm + OFF_VEC;   // alias: [j][nloc], row stride 36
    float* sBL  = sm + OFF_BL;
    float* sBV1 = sm + OFF_BV1;
    float* sV2  = sm + OFF_V2;
    float* sRed = sm + OFF_RED;

    int tid = threadIdx.x;

    // stage weights once per block (persistent blocks)
    for (int i = tid; i < 16384; i += 256) { sW[i] = W_l[i]; sW[16384 + i] = W_r[i]; }
    for (int i = tid; i < 8192;  i += 256) sV1[i] = W_v1[i];
    if (tid < 128) sBL[tid] = b_l[tid];
    if (tid < 64)  { sBV1[tid] = b_v1[tid]; sV2[tid] = W_v2[tid]; }
    __syncthreads();

    const int og  = tid & 31;   // output group (4 outs)
    const int ng  = tid >> 5;   // node group (4 nodes)
    const int ug  = tid & 15;   // hidden-unit group (4 units)
    const int ng2 = tid >> 4;   // node group for head (2 nodes)

    float vsum = 0.f;
    int nTiles = (n + 31) >> 5;

    for (int tile = blockIdx.x; tile < nTiles; tile += gridDim.x) {
        int base = tile << 5;

        // ---- load vec tile [256][32]: k<128 = agg/cnt, k>=128 = a1 ----
        {
            int nloc0 = tid >> 7;      // 0/1
            int k0 = tid & 127;
            #pragma unroll
            for (int it = 0; it < 16; ++it) {
                int nl = it * 2 + nloc0;
                int node = base + nl;
                float av = 0.f, bv = 0.f;
                if (node < n) {
                    av = g_agg[node * F + k0] * g_cinv[node];
                    bv = g_a1[node * F + k0];
                }
                sVec[k0 * 36 + nl]        = av;
                sVec[(128 + k0) * 36 + nl] = bv;
            }
        }
        __syncthreads();

        // ---- a2 GEMM: 32 nodes x 128 outs, K=256, 4x4 register tile ----
        float acc[4][4] = {};
        const float* wp = sW + og * 4;
        const float* vp = sVec + ng * 4;
        #pragma unroll 4
        for (int k = 0; k < 256; ++k) {
            float4 v = *reinterpret_cast<const float4*>(vp + k * 36);
            float4 w = *reinterpret_cast<const float4*>(wp + k * 128);
            float vv[4] = {v.x, v.y, v.z, v.w};
            float ww[4] = {w.x, w.y, w.z, w.w};
            #pragma unroll
            for (int i = 0; i < 4; ++i)
                #pragma unroll
                for (int j = 0; j < 4; ++j)
                    acc[i][j] += vv[i] * ww[j];
        }
        __syncthreads();   // all reads of sVec done (sA2 aliases it)

        // ---- write a2 (+bias) transposed [out][node] ----
        #pragma unroll
        for (int j = 0; j < 4; ++j) {
            float bj = sBL[og * 4 + j];
            #pragma unroll
            for (int i = 0; i < 4; ++i)
                sA2[(og * 4 + j) * 36 + (ng * 4 + i)] = acc[i][j] + bj;
        }
        __syncthreads();

        // ---- value head: hidden = relu(a2 @ W_v1 + b_v1); v = hidden @ W_v2 ----
        float acc2[2][4] = {};
        const float* ap  = sA2 + ng2 * 2;
        const float* w1p = sV1 + ug * 4;
        #pragma unroll 4
        for (int k = 0; k < 128; ++k) {
            float2 a = *reinterpret_cast<const float2*>(ap + k * 36);
            float4 w = *reinterpret_cast<const float4*>(w1p + k * 64);
            float aa[2] = {a.x, a.y};
            float ww[4] = {w.x, w.y, w.z, w.w};
            #pragma unroll
            for (int i = 0; i < 2; ++i)
                #pragma unroll
                for (int j = 0; j < 4; ++j)
                    acc2[i][j] += aa[i] * ww[j];
        }
        #pragma unroll
        for (int i = 0; i < 2; ++i) {
            int node = base + ng2 * 2 + i;
            if (node < n) {
                float s = 0.f;
                #pragma unroll
                for (int j = 0; j < 4; ++j) {
                    float h = fmaxf(acc2[i][j] + sBV1[ug * 4 + j], 0.f);
                    s += h * sV2[ug * 4 + j];
                }
                vsum += s;
            }
        }
        __syncthreads();   // protect sVec/sA2 before next tile's loads
    }

    // ---- block reduce + single atomic into out ----
    sRed[tid] = vsum;
    __syncthreads();
    for (int s = 128; s > 0; s >>= 1) {
        if (tid < s) sRed[tid] += sRed[tid + s];
        __syncthreads();
    }
    if (tid == 0) atomicAdd(out, sRed[0]);
}

// ---------------- launch ----------------
extern "C" void kernel_launch(void* const* d_in, const int* in_sizes, int n_in,
                              void* d_out, int out_size) {
    const float* x      = (const float*)d_in[0];
    const int*   ei     = (const int*)  d_in[1];
    const float* W_gcn  = (const float*)d_in[2];
    const float* b_gcn  = (const float*)d_in[3];
    const float* W_l    = (const float*)d_in[4];
    const float* b_l    = (const float*)d_in[5];
    const float* W_r    = (const float*)d_in[6];
    const float* W_v1   = (const float*)d_in[7];
    const float* b_v1   = (const float*)d_in[8];
    const float* W_v2   = (const float*)d_in[9];
    const float* b_v2   = (const float*)d_in[10];

    int n = in_sizes[0];
    int E = in_sizes[1] / 2;
    float* out = (float*)d_out;

    int nsm = 148;
    {
        int dev = 0;
        if (cudaGetDevice(&dev) == cudaSuccess) {
            int v = 0;
            if (cudaDeviceGetAttribute(&v, cudaDevAttrMultiProcessorCount, dev) == cudaSuccess && v > 0)
                nsm = v;
        }
    }
    cudaFuncSetAttribute(k6_fused, cudaFuncAttributeMaxDynamicSharedMemorySize, SMEM_BYTES);

    k0_zero<<<(n + 255) / 256, 256>>>(n, out, b_v2);
    k1_deg<<<(E + 255) / 256, 256>>>(ei, E);
    k2_norm<<<(n + 255) / 256, 256>>>(n);
    k3_gcn_edges<<<(E + 255) / 256, 256>>>(ei, x, E);
    k4_a1<<<(n * F + 255) / 256, 256>>>(x, W_gcn, b_gcn, n);
    k5_scatter<<<(E + 7) / 8, 256>>>(ei, E);   // one warp per edge
    k6_fused<<<nsm, 256, SMEM_BYTES>>>(W_l, b_l, W_r, W_v1, b_v1, W_v2, n, out);
}

// round 16
// speedup vs baseline: 1.0061x; 1.0043x over previous
#include <cuda_runtime.h>
#include <cuda_bf16.h>
#include <cstdint>

#define NN 50000
#define F 128

// ---------------- scratch (static __device__, no allocation) ----------------
__device__ int   g_degOut[NN];
__device__ int   g_degIn[NN];
__device__ float g_Sx[NN];
__device__ float g_Sd[NN];
__device__ float g_dinv[NN];   // rsqrt(in_deg + 1)  (GCN norm, self-loops included)
__device__ float g_cinv[NN];   // 1 / max(in_deg, 1) (SAGE mean)
__device__ float g_a1[NN * F];
__device__ float g_agg[NN * F];

// ---------------- K0: zero counters, init output with n*b_v2 ----------------
__global__ void k0_zero(int n, float* __restrict__ out, const float* __restrict__ b_v2) {
    int i = blockIdx.x * blockDim.x + threadIdx.x;
    if (i < n) {
        g_degOut[i] = 0;
        g_degIn[i]  = 0;
        g_Sx[i] = 0.f;
        g_Sd[i] = 0.f;
    }
    if (i == 0) out[0] = (float)n * b_v2[0];
}

// ---------------- K1: degree counts ----------------
__global__ void k1_deg(const int* __restrict__ ei, int E) {
    int e = blockIdx.x * blockDim.x + threadIdx.x;
    if (e < E) {
        atomicAdd(&g_degOut[ei[e]], 1);
        atomicAdd(&g_degIn[ei[E + e]], 1);
    }
}

// ---------------- K2: norms ----------------
__global__ void k2_norm(int n) {
    int i = blockIdx.x * blockDim.x + threadIdx.x;
    if (i < n) {
        float din = (float)g_degIn[i];
        g_dinv[i] = rsqrtf(din + 1.0f);          // deg over d2 includes self loop
        g_cinv[i] = 1.0f / fmaxf(din, 1.0f);     // SAGE mean denominator
    }
}

// ---------------- K3: rank-2 GCN edge aggregation (2 scalar atomics/edge) ----
__global__ void k3_gcn_edges(const int* __restrict__ ei, const float* __restrict__ x, int E) {
    int e = blockIdx.x * blockDim.x + threadIdx.x;
    if (e < E) {
        int s = ei[e];
        int d = ei[E + e];
        float w = g_dinv[s] * g_dinv[d];
        atomicAdd(&g_Sx[d], w * x[s]);
        atomicAdd(&g_Sd[d], w * (float)g_degOut[s]);
    }
}

// ---------------- K4: materialize a1 = relu(GCN), zero agg --------------
__global__ void k4_a1(const float* __restrict__ x, const float* __restrict__ W_gcn,
                      const float* __restrict__ b_gcn, int n) {
    int idx = blockIdx.x * blockDim.x + threadIdx.x;
    if (idx < n * F) {
        int i = idx >> 7;
        int k = idx & 127;
        float di = g_dinv[i];
        float di2 = di * di;
        float sx = g_Sx[i] + di2 * x[i];                      // self-loop term
        float sd = g_Sd[i] + di2 * (float)g_degOut[i];
        float v = sx * W_gcn[k] + sd * W_gcn[F + k] + b_gcn[k];
        g_a1[idx] = fmaxf(v, 0.f);
        g_agg[idx] = 0.f;
    }
}

// ---------------- K5: SAGE scatter — warp per edge, vectorized reductions ----
__device__ __forceinline__ void red_add_v4(float* addr, float4 v) {
    asm volatile("red.global.add.v4.f32 [%0], {%1, %2, %3, %4};"
                 :: "l"(addr), "f"(v.x), "f"(v.y), "f"(v.z), "f"(v.w) : "memory");
}

__global__ void __launch_bounds__(256) k5_scatter(const int* __restrict__ ei, int E) {
    int gw = blockIdx.x * 8 + (threadIdx.x >> 5);  // global warp id = edge id
    int lane = threadIdx.x & 31;
    if (gw < E) {
        int s = ei[gw];
        int d = ei[E + gw];
        float4 v = reinterpret_cast<const float4*>(g_a1)[s * 32 + lane];
        red_add_v4(&g_agg[d * F + lane * 4], v);
    }
}

// ---------------- K6: persistent fused GEMM + value head + sum --------------
// smem float offsets
#define OFF_W    0          // [256][128]   W_L ; W_R  (32768)
#define OFF_V1   32768      // [128][64]    W_v1       (8192)
#define OFF_VEC  40960      // [256][36]    node tile, k-major (9216)  -- aliased by a2 tile
#define OFF_BL   50176      // [128] b_sage_l
#define OFF_BV1  50304      // [64]  b_v1
#define OFF_V2   50368      // [64]  W_v2
#define OFF_RED  50432      // [256] block reduce
#define SMEM_FLOATS 50688
#define SMEM_BYTES  (SMEM_FLOATS * 4)

__global__ void __launch_bounds__(256, 1) k6_fused(
    const float* __restrict__ W_l, const float* __restrict__ b_l,
    const float* __restrict__ W_r, const float* __restrict__ W_v1,
    const float* __restrict__ b_v1, const float* __restrict__ W_v2,
    int n, float* __restrict__ out)
{
    extern __shared__ float sm[];
    float* sW   = sm + OFF_W;
    float* sV1  = sm + OFF_V1;
    float* sVec = sm + OFF_VEC;   // [k][nloc], row stride 36
    float* sA2  = sm + OFF_VEC;   // alias: [j][nloc], row stride 36
    float* sBL  = sm + OFF_BL;
    float* sBV1 = sm + OFF_BV1;
    float* sV2  = sm + OFF_V2;
    float* sRed = sm + OFF_RED;

    int tid = threadIdx.x;

    // stage weights once per block (persistent blocks)
    for (int i = tid; i < 16384; i += 256) { sW[i] = W_l[i]; sW[16384 + i] = W_r[i]; }
    for (int i = tid; i < 8192;  i += 256) sV1[i] = W_v1[i];
    if (tid < 128) sBL[tid] = b_l[tid];
    if (tid < 64)  { sBV1[tid] = b_v1[tid]; sV2[tid] = W_v2[tid]; }
    __syncthreads();

    const int og  = tid & 31;   // output group (4 outs)
    const int ng  = tid >> 5;   // node group (4 nodes)
    const int ug  = tid & 15;   // hidden-unit group (4 units)
    const int ng2 = tid >> 4;   // node group for head (2 nodes)

    float vsum = 0.f;
    int nTiles = (n + 31) >> 5;

    for (int tile = blockIdx.x; tile < nTiles; tile += gridDim.x) {
        int base = tile << 5;

        // ---- load vec tile [256][32]: k<128 = agg/cnt, k>=128 = a1 ----
        {
            int nloc0 = tid >> 7;      // 0/1
            int k0 = tid & 127;
            #pragma unroll
            for (int it = 0; it < 16; ++it) {
                int nl = it * 2 + nloc0;
                int node = base + nl;
                float av = 0.f, bv = 0.f;
                if (node < n) {
                    av = g_agg[node * F + k0] * g_cinv[node];
                    bv = g_a1[node * F + k0];
                }
                sVec[k0 * 36 + nl]        = av;
                sVec[(128 + k0) * 36 + nl] = bv;
            }
        }
        __syncthreads();

        // ---- a2 GEMM: 32 nodes x 128 outs, K=256, 4x4 register tile ----
        float acc[4][4] = {};
        const float* wp = sW + og * 4;
        const float* vp = sVec + ng * 4;
        #pragma unroll 4
        for (int k = 0; k < 256; ++k) {
            float4 v = *reinterpret_cast<const float4*>(vp + k * 36);
            float4 w = *reinterpret_cast<const float4*>(wp + k * 128);
            float vv[4] = {v.x, v.y, v.z, v.w};
            float ww[4] = {w.x, w.y, w.z, w.w};
            #pragma unroll
            for (int i = 0; i < 4; ++i)
                #pragma unroll
                for (int j = 0; j < 4; ++j)
                    acc[i][j] += vv[i] * ww[j];
        }
        __syncthreads();   // all reads of sVec done (sA2 aliases it)

        // ---- write a2 (+bias) transposed [out][node] ----
        #pragma unroll
        for (int j = 0; j < 4; ++j) {
            float bj = sBL[og * 4 + j];
            #pragma unroll
            for (int i = 0; i < 4; ++i)
                sA2[(og * 4 + j) * 36 + (ng * 4 + i)] = acc[i][j] + bj;
        }
        __syncthreads();

        // ---- value head: hidden = relu(a2 @ W_v1 + b_v1); v = hidden @ W_v2 ----
        float acc2[2][4] = {};
        const float* ap  = sA2 + ng2 * 2;
        const float* w1p = sV1 + ug * 4;
        #pragma unroll 4
        for (int k = 0; k < 128; ++k) {
            float2 a = *reinterpret_cast<const float2*>(ap + k * 36);
            float4 w = *reinterpret_cast<const float4*>(w1p + k * 64);
            float aa[2] = {a.x, a.y};
            float ww[4] = {w.x, w.y, w.z, w.w};
            #pragma unroll
            for (int i = 0; i < 2; ++i)
                #pragma unroll
                for (int j = 0; j < 4; ++j)
                    acc2[i][j] += aa[i] * ww[j];
        }
        #pragma unroll
        for (int i = 0; i < 2; ++i) {
            int node = base + ng2 * 2 + i;
            if (node < n) {
                float s = 0.f;
                #pragma unroll
                for (int j = 0; j < 4; ++j) {
                    float h = fmaxf(acc2[i][j] + sBV1[ug * 4 + j], 0.f);
                    s += h * sV2[ug * 4 + j];
                }
                vsum += s;
            }
        }
        __syncthreads();   // protect sVec/sA2 before next tile's loads
    }

    // ---- block reduce + single atomic into out ----
    sRed[tid] = vsum;
    __syncthreads();
    for (int s = 128; s > 0; s >>= 1) {
        if (tid < s) sRed[tid] += sRed[tid + s];
        __syncthreads();
    }
    if (tid == 0) atomicAdd(out, sRed[0]);
}

// ---------------- launch ----------------
extern "C" void kernel_launch(void* const* d_in, const int* in_sizes, int n_in,
                              void* d_out, int out_size) {
    const float* x      = (const float*)d_in[0];
    const int*   ei     = (const int*)  d_in[1];
    const float* W_gcn  = (const float*)d_in[2];
    const float* b_gcn  = (const float*)d_in[3];
    const float* W_l    = (const float*)d_in[4];
    const float* b_l    = (const float*)d_in[5];
    const float* W_r    = (const float*)d_in[6];
    const float* W_v1   = (const float*)d_in[7];
    const float* b_v1   = (const float*)d_in[8];
    const float* W_v2   = (const float*)d_in[9];
    const float* b_v2   = (const float*)d_in[10];

    int n = in_sizes[0];
    int E = in_sizes[1] / 2;
    float* out = (float*)d_out;

    int nsm = 148;
    {
        int dev = 0;
        if (cudaGetDevice(&dev) == cudaSuccess) {
            int v = 0;
            if (cudaDeviceGetAttribute(&v, cudaDevAttrMultiProcessorCount, dev) == cudaSuccess && v > 0)
                nsm = v;
        }
    }
    cudaFuncSetAttribute(k6_fused, cudaFuncAttributeMaxDynamicSharedMemorySize, SMEM_BYTES);

    k0_zero<<<(n + 255) / 256, 256>>>(n, out, b_v2);
    k1_deg<<<(E + 255) / 256, 256>>>(ei, E);
    k2_norm<<<(n + 255) / 256, 256>>>(n);
    k3_gcn_edges<<<(E + 255) / 256, 256>>>(ei, x, E);
    k4_a1<<<(n * F + 255) / 256, 256>>>(x, W_gcn, b_gcn, n);
    k5_scatter<<<(E + 7) / 8, 256>>>(ei, E);   // one warp per edge
    k6_fused<<<nsm, 256, SMEM_BYTES>>>(W_l, b_l, W_r, W_v1, b_v1, W_v2, n, out);
}